// round 10
// baseline (speedup 1.0000x reference)
#include <cuda_runtime.h>
#include <cuda_bf16.h>
#include <cstdint>

#define DIM 64
#define TSTEPS 1000
#define BATCH 1024
#define MSZ (DIM*DIM)   // 4096
#define TLOOP 8

// squaring table M^(2^j), j = 0..9, fp32
__device__ float g_sq[10 * MSZ];
// bf16 2-way split of M^t: [t][plane][i*64+j], planes hi/lo
__device__ __align__(16) __nv_bfloat16 g_powsb[TSTEPS * 2 * MSZ];
// bf16 2-way split of x0: [plane][b*64+j]
__device__ __align__(16) __nv_bfloat16 g_x0s[2 * BATCH * DIM];

// ===========================================================================
// helpers
// ===========================================================================
__device__ __forceinline__ uint32_t smem_to_u32(const void* p) {
    uint32_t a;
    asm("{ .reg .u64 t; cvta.to.shared.u64 t, %1; cvt.u32.u64 %0, t; }"
        : "=r"(a) : "l"(p));
    return a;
}

__device__ __forceinline__ void split2(float v, __nv_bfloat16& h, __nv_bfloat16& l) {
    h = __float2bfloat16(v);
    l = __float2bfloat16(v - __bfloat162float(h));
}

// ldmatrix x4: 4 8x8 b16 tiles, addresses from all 32 lanes
#define LDSM_X4(r, addr) \
    asm volatile("ldmatrix.sync.aligned.m8n8.x4.shared.b16 {%0,%1,%2,%3}, [%4];" \
        : "=r"((r)[0]), "=r"((r)[1]), "=r"((r)[2]), "=r"((r)[3]) : "r"(addr))

// bf16 HMMA, fp32 accumulate in place
#define MMA16816(d, a, b) \
    asm volatile("mma.sync.aligned.m16n8k16.row.col.f32.bf16.bf16.f32 " \
        "{%0,%1,%2,%3}, {%4,%5,%6,%7}, {%8,%9}, {%0,%1,%2,%3};" \
        : "+f"((d)[0]), "+f"((d)[1]), "+f"((d)[2]), "+f"((d)[3]) \
        : "r"((a)[0]), "r"((a)[1]), "r"((a)[2]), "r"((a)[3]), \
          "r"((b)[0]), "r"((b)[1]))

// ===========================================================================
// 64x64 matmul helper (smem->smem), 256 threads, 4x4 tiles.
// Safe for C aliasing A or B (sync between read loop and stores).
// ===========================================================================
__device__ __forceinline__ void mm64(const float* A, const float* B, float* C) {
    __syncthreads();
    int tid = threadIdx.x;
    int i0 = (tid >> 4) << 2;
    int j0 = (tid & 15) << 2;
    float acc[4][4];
#pragma unroll
    for (int r = 0; r < 4; r++)
#pragma unroll
        for (int c = 0; c < 4; c++) acc[r][c] = 0.0f;
#pragma unroll 8
    for (int l = 0; l < 64; l++) {
        float a0 = A[(i0 + 0) * 64 + l];
        float a1 = A[(i0 + 1) * 64 + l];
        float a2 = A[(i0 + 2) * 64 + l];
        float a3 = A[(i0 + 3) * 64 + l];
        float4 b4 = *(const float4*)(B + l * 64 + j0);
        float bb[4] = {b4.x, b4.y, b4.z, b4.w};
#pragma unroll
        for (int c = 0; c < 4; c++) {
            acc[0][c] += a0 * bb[c];
            acc[1][c] += a1 * bb[c];
            acc[2][c] += a2 * bb[c];
            acc[3][c] += a3 * bb[c];
        }
    }
    __syncthreads();
#pragma unroll
    for (int r = 0; r < 4; r++)
        *(float4*)(C + (i0 + r) * 64 + j0) =
            make_float4(acc[r][0], acc[r][1], acc[r][2], acc[r][3]);
    __syncthreads();
}

// ===========================================================================
// Kernel 0: split x0 into bf16 pairs
// ===========================================================================
__global__ void split_x0_kernel(const float* __restrict__ inputs) {
    int idx = blockIdx.x * 256 + threadIdx.x;   // 0..65535
    int b = idx >> 6, j = idx & 63;
    float v = inputs[(size_t)b * (TSTEPS * DIM) + j];
    __nv_bfloat16 h, l;
    split2(v, h, l);
    g_x0s[idx] = h;
    g_x0s[65536 + idx] = l;
}

// ===========================================================================
// Kernel 1: M = expm(K) (degree-14 Paterson-Stockmeyer Taylor), then
// 9 in-smem squarings. Writes g_sq[j] = M^(2^j), j = 0..9. One CTA.
// ===========================================================================
__global__ void expm_sq_kernel(const float* __restrict__ Kin) {
    extern __shared__ float smf[];
    float* sK  = smf;
    float* sK2 = smf + MSZ;
    float* sK3 = smf + 2 * MSZ;
    float* sS  = smf + 3 * MSZ;
    float* sT  = smf + 4 * MSZ;
    int tid = threadIdx.x;

    const float c[15] = {
        1.0f, 1.0f, 0.5f,
        1.6666666666666666e-1f, 4.1666666666666664e-2f, 8.3333333333333332e-3f,
        1.3888888888888889e-3f, 1.9841269841269841e-4f, 2.4801587301587302e-5f,
        2.7557319223985893e-6f, 2.7557319223985888e-7f, 2.5052108385441720e-8f,
        2.0876756987868100e-9f, 1.6059043836821613e-10f, 1.1470745597729725e-11f
    };

#pragma unroll
    for (int q = 0; q < 16; q++) sK[tid + 256 * q] = Kin[tid + 256 * q];

    mm64(sK, sK, sK2);
    mm64(sK2, sK, sK3);

#pragma unroll
    for (int q = 0; q < 16; q++) {
        int e = tid + 256 * q;
        int i = e >> 6, j = e & 63;
        sS[e] = (i == j ? c[12] : 0.0f) + c[13] * sK[e] + c[14] * sK2[e];
    }
    for (int m = 3; m >= 0; m--) {
        mm64(sK3, sS, sT);
#pragma unroll
        for (int q = 0; q < 16; q++) {
            int e = tid + 256 * q;
            int i = e >> 6, j = e & 63;
            sS[e] = sT[e] + (i == j ? c[3 * m] : 0.0f)
                  + c[3 * m + 1] * sK[e] + c[3 * m + 2] * sK2[e];
        }
        __syncthreads();
    }

    // sS = M. Store S_0, then square 9 times.
#pragma unroll
    for (int q = 0; q < 16; q++) {
        int e = tid + 256 * q;
        g_sq[e] = sS[e];
    }
    for (int j = 1; j <= 9; j++) {
        mm64(sS, sS, sS);       // in-place safe
#pragma unroll
        for (int q = 0; q < 16; q++) {
            int e = tid + 256 * q;
            g_sq[j * MSZ + e] = sS[e];
        }
    }
}

// ===========================================================================
// Kernel 2: per-t binary product. CTA t computes M^t = prod over set bits
// of g_sq[j] (commuting factors), writes bf16 hi/lo split. 1000 CTAs.
// ===========================================================================
__global__ void power_kernel() {
    __shared__ __align__(16) float sA[MSZ];
    __shared__ __align__(16) float sB[MSZ];
    int t = blockIdx.x;
    int tid = threadIdx.x;
    size_t sb = (size_t)t * 2 * MSZ;

    if (t == 0) {   // identity, exact in bf16
#pragma unroll
        for (int q = 0; q < 16; q++) {
            int e = tid + 256 * q;
            int i = e >> 6, j = e & 63;
            g_powsb[sb + e] = __float2bfloat16(i == j ? 1.0f : 0.0f);
            g_powsb[sb + MSZ + e] = __float2bfloat16(0.0f);
        }
        return;
    }

    int j0 = __ffs(t) - 1;
    const float* S0 = g_sq + (size_t)j0 * MSZ;
#pragma unroll
    for (int q = 0; q < 16; q++) {
        int e = tid + 256 * q;
        sA[e] = S0[e];
    }
    for (int j = j0 + 1; j <= 9; j++) {
        if ((t >> j) & 1) {
            __syncthreads();    // prior mm64 stores done before sB overwrite? (mm64 ends synced; this also covers the first iteration's sA fill)
            const float* Sj = g_sq + (size_t)j * MSZ;
#pragma unroll
            for (int q = 0; q < 16; q++) {
                int e = tid + 256 * q;
                sB[e] = Sj[e];
            }
            mm64(sA, sB, sA);   // entry sync orders sB fill before reads
        }
    }
    __syncthreads();
#pragma unroll
    for (int q = 0; q < 16; q++) {
        int e = tid + 256 * q;
        float v = sA[e];
        __nv_bfloat16 hh, ll;
        split2(v, hh, ll);
        g_powsb[sb + e] = hh;
        g_powsb[sb + MSZ + e] = ll;
    }
}

// ===========================================================================
// Kernel 3: HMMA (mma.sync bf16x2-split) GEMM. (unchanged, validated)
// CTA: 128 batch x 64 out-dim x TLOOP t's. 256 threads, 8 warps.
// ===========================================================================
#define ASTRIDE 144                 // bytes per padded row
#define A_PLANE 18432               // 128 rows * 144B
#define B_PLANE 9216                // 64 rows * 144B
#define SM_B    (2 * A_PLANE)       // 36864: A hi, A lo
#define B_BUF   (2 * B_PLANE)       // 18432 per buffer (hi+lo)
#define SM_TOT  (SM_B + 2 * B_BUF)  // 73728

__global__ __launch_bounds__(256, 2)
void gemm_mma_kernel(float* __restrict__ out) {
    extern __shared__ char smc[];
    uint32_t sbase = smem_to_u32(smc);
    int tid = threadIdx.x;
    int w = tid >> 5, lane = tid & 31;
    int b0 = blockIdx.x << 7;
    int tbase = blockIdx.y * TLOOP;

    // ---- stage A: 2 planes x 128 rows x 64 bf16, padded rows ----
#pragma unroll
    for (int q = 0; q < 8; q++) {
        int e = tid + 256 * q;          // 0..2047
        int p = e >> 10, rem = e & 1023;
        int row = rem >> 3, c = rem & 7;
        uint4 v = *(const uint4*)(g_x0s + p * (BATCH * DIM) + (b0 + row) * 64 + c * 8);
        *(uint4*)(smc + p * A_PLANE + row * ASTRIDE + c * 16) = v;
    }
    // ---- stage B buffer 0 for t = tbase ----
    {
        const __nv_bfloat16* src = g_powsb + (size_t)tbase * 2 * MSZ;
#pragma unroll
        for (int q = 0; q < 4; q++) {
            int e = tid + 256 * q;      // 0..1023
            int p = e >> 9, rem = e & 511;
            int row = rem >> 3, c = rem & 7;
            uint4 v = *(const uint4*)(src + p * MSZ + row * 64 + c * 8);
            *(uint4*)(smc + SM_B + p * B_PLANE + row * ASTRIDE + c * 16) = v;
        }
    }
    __syncthreads();

    // ---- A fragments, persistent across the whole t loop ----
    uint32_t aH[4][4], aL[4][4];
    {
        uint32_t arow = sbase + (w * 16 + (lane & 15)) * ASTRIDE + (lane >> 4) * 16;
#pragma unroll
        for (int k = 0; k < 4; k++) {
            LDSM_X4(aH[k], arow + k * 32);
            LDSM_X4(aL[k], arow + A_PLANE + k * 32);
        }
    }

    uint32_t brow_off = (((lane >> 4) << 3) + (lane & 7)) * ASTRIDE
                      + ((lane >> 3) & 1) * 16;

    int cur = 0;
#pragma unroll 1
    for (int it = 0; it < TLOOP; it++) {
        int t = tbase + it;

        // ---- prefetch next B into the other buffer ----
        if (it + 1 < TLOOP) {
            const __nv_bfloat16* src = g_powsb + (size_t)(t + 1) * 2 * MSZ;
#pragma unroll
            for (int q = 0; q < 4; q++) {
                int e = tid + 256 * q;
                int p = e >> 9, rem = e & 511;
                int row = rem >> 3, c = rem & 7;
                uint4 v = *(const uint4*)(src + p * MSZ + row * 64 + c * 8);
                *(uint4*)(smc + SM_B + (1 - cur) * B_BUF + p * B_PLANE
                          + row * ASTRIDE + c * 16) = v;
            }
        }

        // ---- compute from current buffer ----
        float acc[8][4];
#pragma unroll
        for (int nt = 0; nt < 8; nt++)
#pragma unroll
            for (int c = 0; c < 4; c++) acc[nt][c] = 0.0f;

        uint32_t bb = sbase + SM_B + cur * B_BUF + brow_off;
#pragma unroll
        for (int k = 0; k < 4; k++) {
            uint32_t bH[8][2], bL[8][2];
#pragma unroll
            for (int p = 0; p < 4; p++) {
                uint32_t addr = bb + p * 16 * ASTRIDE + k * 32;
                LDSM_X4(&bH[2 * p][0], addr);
                LDSM_X4(&bL[2 * p][0], addr + B_PLANE);
            }
#pragma unroll
            for (int nt = 0; nt < 8; nt++) {
                MMA16816(acc[nt], aH[k], bH[nt]);   // hi*hi
                MMA16816(acc[nt], aH[k], bL[nt]);   // hi*lo
                MMA16816(acc[nt], aL[k], bH[nt]);   // lo*hi
            }
        }

        // ---- store C frags ----
        {
            int g = lane >> 2, tq = lane & 3;
            size_t r0 = (size_t)b0 + w * 16 + g;
            float* o0 = out + (r0 * TSTEPS + t) * DIM + 2 * tq;
            float* o1 = o0 + (size_t)8 * TSTEPS * DIM;
#pragma unroll
            for (int nt = 0; nt < 8; nt++) {
                *(float2*)(o0 + nt * 8) = make_float2(acc[nt][0], acc[nt][1]);
                *(float2*)(o1 + nt * 8) = make_float2(acc[nt][2], acc[nt][3]);
            }
        }

        __syncthreads();
        cur ^= 1;
    }
}

// ===========================================================================
extern "C" void kernel_launch(void* const* d_in, const int* in_sizes, int n_in,
                              void* d_out, int out_size) {
    const float* inputs = (const float*)d_in[0];
    const float* kern   = (const float*)d_in[1];
    if (in_sizes[0] == MSZ) {   // defensive: metadata order swap
        const float* tmp = inputs; inputs = kern; kern = tmp;
    }
    float* out = (float*)d_out;

    cudaFuncSetAttribute(expm_sq_kernel, cudaFuncAttributeMaxDynamicSharedMemorySize,
                         5 * MSZ * 4);
    cudaFuncSetAttribute(gemm_mma_kernel, cudaFuncAttributeMaxDynamicSharedMemorySize,
                         SM_TOT);

    split_x0_kernel<<<256, 256>>>(inputs);
    expm_sq_kernel<<<1, 256, 5 * MSZ * 4>>>(kern);
    power_kernel<<<TSTEPS, 256>>>();

    dim3 grid(BATCH / 128, TSTEPS / TLOOP);   // (8, 125)
    gemm_mma_kernel<<<grid, 256, SM_TOT>>>(out);
}

// round 11
// speedup vs baseline: 1.4237x; 1.4237x over previous
#include <cuda_runtime.h>
#include <cuda_bf16.h>
#include <cstdint>

#define DIM 64
#define TSTEPS 1000
#define BATCH 1024
#define MSZ (DIM*DIM)   // 4096
#define TLOOP 8

// squaring table M^(2^j), j = 0..9, fp32
__device__ float g_sq[10 * MSZ];
// two-level tables: low[r] = M^r (r<32), high[q] = M^(32q) (q<32)
__device__ float g_low[32 * MSZ];
__device__ float g_high[32 * MSZ];
// bf16 2-way split of M^t: [t][plane][i*64+j], planes hi/lo
__device__ __align__(16) __nv_bfloat16 g_powsb[TSTEPS * 2 * MSZ];
// bf16 2-way split of x0: [plane][b*64+j]
__device__ __align__(16) __nv_bfloat16 g_x0s[2 * BATCH * DIM];

// ===========================================================================
// helpers
// ===========================================================================
__device__ __forceinline__ uint32_t smem_to_u32(const void* p) {
    uint32_t a;
    asm("{ .reg .u64 t; cvta.to.shared.u64 t, %1; cvt.u32.u64 %0, t; }"
        : "=r"(a) : "l"(p));
    return a;
}

__device__ __forceinline__ void split2(float v, __nv_bfloat16& h, __nv_bfloat16& l) {
    h = __float2bfloat16(v);
    l = __float2bfloat16(v - __bfloat162float(h));
}

// ldmatrix x4: 4 8x8 b16 tiles
#define LDSM_X4(r, addr) \
    asm volatile("ldmatrix.sync.aligned.m8n8.x4.shared.b16 {%0,%1,%2,%3}, [%4];" \
        : "=r"((r)[0]), "=r"((r)[1]), "=r"((r)[2]), "=r"((r)[3]) : "r"(addr))

// ldmatrix x4 transposed (for row-major B operand)
#define LDSM_X4_T(r, addr) \
    asm volatile("ldmatrix.sync.aligned.m8n8.x4.trans.shared.b16 {%0,%1,%2,%3}, [%4];" \
        : "=r"((r)[0]), "=r"((r)[1]), "=r"((r)[2]), "=r"((r)[3]) : "r"(addr))

// bf16 HMMA, fp32 accumulate in place
#define MMA16816(d, a, b) \
    asm volatile("mma.sync.aligned.m16n8k16.row.col.f32.bf16.bf16.f32 " \
        "{%0,%1,%2,%3}, {%4,%5,%6,%7}, {%8,%9}, {%0,%1,%2,%3};" \
        : "+f"((d)[0]), "+f"((d)[1]), "+f"((d)[2]), "+f"((d)[3]) \
        : "r"((a)[0]), "r"((a)[1]), "r"((a)[2]), "r"((a)[3]), \
          "r"((b)[0]), "r"((b)[1]))

// ===========================================================================
// mm64_tc: C(64x64 fp32, SMEM) = A @ B, A/B fp32 row-major (SMEM or GMEM ok),
// via 2-way bf16 split + 3-cross HMMA. 256 threads. C may alias A/B if those
// are SMEM (inputs consumed into bf16 planes before C is written).
// scr: 36864B SMEM scratch (4 planes of 64 rows x 144B).
// ===========================================================================
#define PL 9216     // plane bytes: 64 rows * 144
__device__ void mm64_tc(const float* A, const float* B, float* C, char* scr) {
    uint32_t scrb = smem_to_u32(scr);
    int tid = threadIdx.x;
    __syncthreads();
    // ---- split A, B into bf16 hi/lo planes (padded 144B rows) ----
#pragma unroll
    for (int q = 0; q < 8; q++) {
        int e2 = tid + 256 * q;        // 0..2047
        int row = e2 >> 5, cp = e2 & 31;   // col pair
        float2 a = *(const float2*)(A + row * 64 + cp * 2);
        float2 b = *(const float2*)(B + row * 64 + cp * 2);
        __nv_bfloat16 h0, l0, h1, l1;
        split2(a.x, h0, l0); split2(a.y, h1, l1);
        *(__nv_bfloat162*)(scr + 0 * PL + row * 144 + cp * 4) = {h0, h1};
        *(__nv_bfloat162*)(scr + 1 * PL + row * 144 + cp * 4) = {l0, l1};
        split2(b.x, h0, l0); split2(b.y, h1, l1);
        *(__nv_bfloat162*)(scr + 2 * PL + row * 144 + cp * 4) = {h0, h1};
        *(__nv_bfloat162*)(scr + 3 * PL + row * 144 + cp * 4) = {l0, l1};
    }
    __syncthreads();
    // ---- warp tiling: warp w = (mt = w&3) x (nh = w>>2); 16 rows x 32 cols ----
    int w = tid >> 5, lane = tid & 31;
    int mt = w & 3, nh = w >> 2;
    float acc[4][4];
#pragma unroll
    for (int nt = 0; nt < 4; nt++)
#pragma unroll
        for (int c = 0; c < 4; c++) acc[nt][c] = 0.0f;

    uint32_t a_base = scrb + (16 * mt + (lane & 15)) * 144 + ((lane >> 4) * 8) * 2;
#pragma unroll
    for (int k0 = 0; k0 < 64; k0 += 16) {
        uint32_t aH[4], aL[4];
        LDSM_X4(aH, a_base + k0 * 2);
        LDSM_X4(aL, a_base + PL + k0 * 2);
#pragma unroll
        for (int np = 0; np < 2; np++) {
            int n0 = 32 * nh + np * 16;
            uint32_t b_addr = scrb + 2 * PL + (k0 + (lane & 15)) * 144
                            + (n0 + (lane >> 4) * 8) * 2;
            uint32_t bH[4], bL[4];
            LDSM_X4_T(bH, b_addr);
            LDSM_X4_T(bL, b_addr + PL);
            MMA16816(acc[2 * np + 0], aH, &bH[0]);
            MMA16816(acc[2 * np + 0], aH, &bL[0]);
            MMA16816(acc[2 * np + 0], aL, &bH[0]);
            MMA16816(acc[2 * np + 1], aH, &bH[2]);
            MMA16816(acc[2 * np + 1], aH, &bL[2]);
            MMA16816(acc[2 * np + 1], aL, &bH[2]);
        }
    }
    __syncthreads();   // planes fully consumed; safe to overwrite C (alias A/B)
    int g = lane >> 2, qd = lane & 3;
#pragma unroll
    for (int nt = 0; nt < 4; nt++) {
        int col = 32 * nh + 8 * nt + 2 * qd;
        *(float2*)(C + (16 * mt + g) * 64 + col) = make_float2(acc[nt][0], acc[nt][1]);
        *(float2*)(C + (16 * mt + g + 8) * 64 + col) = make_float2(acc[nt][2], acc[nt][3]);
    }
    __syncthreads();
}

// ===========================================================================
// Kernel 1: M = expm(K) (degree-14 PS Taylor, tc multiplies), then 9 tc
// squarings. Writes g_sq[j] = M^(2^j), j = 0..9. One CTA, 256 threads.
// Dyn smem: 5 fp32 bufs (80KB) + 36864 scratch.
// ===========================================================================
#define L1_SMEM (5 * MSZ * 4 + 4 * PL)
__global__ void expm_sq_kernel(const float* __restrict__ Kin) {
    extern __shared__ float smf[];
    float* sK  = smf;
    float* sK2 = smf + MSZ;
    float* sK3 = smf + 2 * MSZ;
    float* sS  = smf + 3 * MSZ;
    float* sT  = smf + 4 * MSZ;
    char* scr = (char*)(smf + 5 * MSZ);
    int tid = threadIdx.x;

    const float c[15] = {
        1.0f, 1.0f, 0.5f,
        1.6666666666666666e-1f, 4.1666666666666664e-2f, 8.3333333333333332e-3f,
        1.3888888888888889e-3f, 1.9841269841269841e-4f, 2.4801587301587302e-5f,
        2.7557319223985893e-6f, 2.7557319223985888e-7f, 2.5052108385441720e-8f,
        2.0876756987868100e-9f, 1.6059043836821613e-10f, 1.1470745597729725e-11f
    };

#pragma unroll
    for (int q = 0; q < 16; q++) sK[tid + 256 * q] = Kin[tid + 256 * q];

    mm64_tc(sK, sK, sK2, scr);     // K^2
    mm64_tc(sK2, sK, sK3, scr);    // K^3

#pragma unroll
    for (int q = 0; q < 16; q++) {
        int e = tid + 256 * q;
        int i = e >> 6, j = e & 63;
        sS[e] = (i == j ? c[12] : 0.0f) + c[13] * sK[e] + c[14] * sK2[e];
    }
    __syncthreads();
    for (int m = 3; m >= 0; m--) {
        mm64_tc(sK3, sS, sT, scr);
#pragma unroll
        for (int q = 0; q < 16; q++) {
            int e = tid + 256 * q;
            int i = e >> 6, j = e & 63;
            sS[e] = sT[e] + (i == j ? c[3 * m] : 0.0f)
                  + c[3 * m + 1] * sK[e] + c[3 * m + 2] * sK2[e];
        }
        __syncthreads();
    }

    // sS = M. Store sq[0], then 9 squarings (in-place safe).
#pragma unroll
    for (int q = 0; q < 16; q++) g_sq[tid + 256 * q] = sS[tid + 256 * q];
    for (int j = 1; j <= 9; j++) {
        mm64_tc(sS, sS, sS, scr);
#pragma unroll
        for (int q = 0; q < 16; q++)
            g_sq[j * MSZ + tid + 256 * q] = sS[tid + 256 * q];
    }
}

// ===========================================================================
// Kernel 2 (grid 320): CTAs 0..63 build two-level tables
//   i < 32 : g_low[i]  = prod over bits j of i  of sq[j]      (M^i)
//   i >= 32: g_high[i-32] = prod over bits j of sq[5+j]        (M^(32q))
// CTAs 64..319: split x0 into bf16 pairs.
// Dyn smem: sA 16KB + scratch 36864.
// ===========================================================================
#define L23_SMEM (MSZ * 4 + 4 * PL)
__global__ void tables_kernel(const float* __restrict__ inputs) {
    extern __shared__ float smf[];
    float* sA = smf;
    char* scr = (char*)(smf + MSZ);
    int bid = blockIdx.x;
    int tid = threadIdx.x;

    if (bid >= 64) {   // x0 split
        int idx = (bid - 64) * 256 + tid;   // 0..65535
        int b = idx >> 6, j = idx & 63;
        float v = inputs[(size_t)b * (TSTEPS * DIM) + j];
        __nv_bfloat16 h, l;
        split2(v, h, l);
        g_x0s[idx] = h;
        g_x0s[65536 + idx] = l;
        return;
    }

    int n = bid & 31;
    int base = (bid < 32) ? 0 : 5;
    float* dst = (bid < 32 ? g_low : g_high) + (size_t)n * MSZ;

    if (n == 0) {   // identity
#pragma unroll
        for (int q = 0; q < 16; q++) {
            int e = tid + 256 * q;
            dst[e] = ((e >> 6) == (e & 63)) ? 1.0f : 0.0f;
        }
        return;
    }

    int j0 = __ffs(n) - 1;
    const float* first = g_sq + (size_t)(base + j0) * MSZ;
    bool in_smem = false;
    for (int j = j0 + 1; j < 5; j++) {
        if ((n >> j) & 1) {
            const float* fac = g_sq + (size_t)(base + j) * MSZ;
            mm64_tc(in_smem ? sA : first, fac, sA, scr);
            in_smem = true;
        }
    }
    if (!in_smem) {   // n is a power of two: direct copy
#pragma unroll
        for (int q = 0; q < 16; q++) {
            int e = tid + 256 * q;
            dst[e] = first[e];
        }
        return;
    }
#pragma unroll
    for (int q = 0; q < 16; q++) {
        int e = tid + 256 * q;
        dst[e] = sA[e];
    }
}

// ===========================================================================
// Kernel 3 (grid 1000): M^t = high[t>>5] @ low[t&31] (one tc multiply),
// write bf16 hi/lo split to g_powsb.
// ===========================================================================
__global__ void power_kernel() {
    extern __shared__ float smf[];
    float* sA = smf;
    char* scr = (char*)(smf + MSZ);
    int t = blockIdx.x;
    int tid = threadIdx.x;
    int q5 = t >> 5, r = t & 31;

    mm64_tc(g_high + (size_t)q5 * MSZ, g_low + (size_t)r * MSZ, sA, scr);

    size_t sb = (size_t)t * 2 * MSZ;
#pragma unroll
    for (int q = 0; q < 16; q++) {
        int e = tid + 256 * q;
        __nv_bfloat16 hh, ll;
        split2(sA[e], hh, ll);
        g_powsb[sb + e] = hh;
        g_powsb[sb + MSZ + e] = ll;
    }
}

// ===========================================================================
// Kernel 4: HMMA gemm (unchanged, validated at 96.7us).
// ===========================================================================
#define ASTRIDE 144
#define A_PLANE 18432
#define B_PLANE 9216
#define SM_B    (2 * A_PLANE)
#define B_BUF   (2 * B_PLANE)
#define SM_TOT  (SM_B + 2 * B_BUF)

__global__ __launch_bounds__(256, 2)
void gemm_mma_kernel(float* __restrict__ out) {
    extern __shared__ char smc[];
    uint32_t sbase = smem_to_u32(smc);
    int tid = threadIdx.x;
    int w = tid >> 5, lane = tid & 31;
    int b0 = blockIdx.x << 7;
    int tbase = blockIdx.y * TLOOP;

#pragma unroll
    for (int q = 0; q < 8; q++) {
        int e = tid + 256 * q;
        int p = e >> 10, rem = e & 1023;
        int row = rem >> 3, c = rem & 7;
        uint4 v = *(const uint4*)(g_x0s + p * (BATCH * DIM) + (b0 + row) * 64 + c * 8);
        *(uint4*)(smc + p * A_PLANE + row * ASTRIDE + c * 16) = v;
    }
    {
        const __nv_bfloat16* src = g_powsb + (size_t)tbase * 2 * MSZ;
#pragma unroll
        for (int q = 0; q < 4; q++) {
            int e = tid + 256 * q;
            int p = e >> 9, rem = e & 511;
            int row = rem >> 3, c = rem & 7;
            uint4 v = *(const uint4*)(src + p * MSZ + row * 64 + c * 8);
            *(uint4*)(smc + SM_B + p * B_PLANE + row * ASTRIDE + c * 16) = v;
        }
    }
    __syncthreads();

    uint32_t aH[4][4], aL[4][4];
    {
        uint32_t arow = sbase + (w * 16 + (lane & 15)) * ASTRIDE + (lane >> 4) * 16;
#pragma unroll
        for (int k = 0; k < 4; k++) {
            LDSM_X4(aH[k], arow + k * 32);
            LDSM_X4(aL[k], arow + A_PLANE + k * 32);
        }
    }

    uint32_t brow_off = (((lane >> 4) << 3) + (lane & 7)) * ASTRIDE
                      + ((lane >> 3) & 1) * 16;

    int cur = 0;
#pragma unroll 1
    for (int it = 0; it < TLOOP; it++) {
        int t = tbase + it;

        if (it + 1 < TLOOP) {
            const __nv_bfloat16* src = g_powsb + (size_t)(t + 1) * 2 * MSZ;
#pragma unroll
            for (int q = 0; q < 4; q++) {
                int e = tid + 256 * q;
                int p = e >> 9, rem = e & 511;
                int row = rem >> 3, c = rem & 7;
                uint4 v = *(const uint4*)(src + p * MSZ + row * 64 + c * 8);
                *(uint4*)(smc + SM_B + (1 - cur) * B_BUF + p * B_PLANE
                          + row * ASTRIDE + c * 16) = v;
            }
        }

        float acc[8][4];
#pragma unroll
        for (int nt = 0; nt < 8; nt++)
#pragma unroll
            for (int c = 0; c < 4; c++) acc[nt][c] = 0.0f;

        uint32_t bb = sbase + SM_B + cur * B_BUF + brow_off;
#pragma unroll
        for (int k = 0; k < 4; k++) {
            uint32_t bH[8][2], bL[8][2];
#pragma unroll
            for (int p = 0; p < 4; p++) {
                uint32_t addr = bb + p * 16 * ASTRIDE + k * 32;
                LDSM_X4(&bH[2 * p][0], addr);
                LDSM_X4(&bL[2 * p][0], addr + B_PLANE);
            }
#pragma unroll
            for (int nt = 0; nt < 8; nt++) {
                MMA16816(acc[nt], aH[k], bH[nt]);
                MMA16816(acc[nt], aH[k], bL[nt]);
                MMA16816(acc[nt], aL[k], bH[nt]);
            }
        }

        {
            int g = lane >> 2, tq = lane & 3;
            size_t r0 = (size_t)b0 + w * 16 + g;
            float* o0 = out + (r0 * TSTEPS + t) * DIM + 2 * tq;
            float* o1 = o0 + (size_t)8 * TSTEPS * DIM;
#pragma unroll
            for (int nt = 0; nt < 8; nt++) {
                *(float2*)(o0 + nt * 8) = make_float2(acc[nt][0], acc[nt][1]);
                *(float2*)(o1 + nt * 8) = make_float2(acc[nt][2], acc[nt][3]);
            }
        }

        __syncthreads();
        cur ^= 1;
    }
}

// ===========================================================================
extern "C" void kernel_launch(void* const* d_in, const int* in_sizes, int n_in,
                              void* d_out, int out_size) {
    const float* inputs = (const float*)d_in[0];
    const float* kern   = (const float*)d_in[1];
    if (in_sizes[0] == MSZ) {   // defensive: metadata order swap
        const float* tmp = inputs; inputs = kern; kern = tmp;
    }
    float* out = (float*)d_out;

    cudaFuncSetAttribute(expm_sq_kernel, cudaFuncAttributeMaxDynamicSharedMemorySize,
                         L1_SMEM);
    cudaFuncSetAttribute(tables_kernel, cudaFuncAttributeMaxDynamicSharedMemorySize,
                         L23_SMEM);
    cudaFuncSetAttribute(power_kernel, cudaFuncAttributeMaxDynamicSharedMemorySize,
                         L23_SMEM);
    cudaFuncSetAttribute(gemm_mma_kernel, cudaFuncAttributeMaxDynamicSharedMemorySize,
                         SM_TOT);

    expm_sq_kernel<<<1, 256, L1_SMEM>>>(kern);
    tables_kernel<<<320, 256, L23_SMEM>>>(inputs);
    power_kernel<<<TSTEPS, 256, L23_SMEM>>>();

    dim3 grid(BATCH / 128, TSTEPS / TLOOP);   // (8, 125)
    gemm_mma_kernel<<<grid, 256, SM_TOT>>>(out);
}